// round 1
// baseline (speedup 1.0000x reference)
#include <cuda_runtime.h>
#include <math.h>

// ---------------------------------------------------------------------------
// Problem constants
// ---------------------------------------------------------------------------
#define BATCH   16
#define CDIM    512
#define NTOK    1024          // H*W = 32*32
#define NHEADS  8
#define DK      64
#define MTOT    (BATCH * NTOK)        // 16384
#define QKVOUT  (NHEADS * DK * 3)     // 1536
#define ODIM    (NHEADS * DK)         // 512

// ---------------------------------------------------------------------------
// Scratch (device globals; no runtime allocation allowed)
// ---------------------------------------------------------------------------
__device__ float g_q[BATCH * NHEADS * NTOK * DK];   // [b,h,n,d]
__device__ float g_k[BATCH * NHEADS * NTOK * DK];
__device__ float g_v[BATCH * NHEADS * NTOK * DK];
__device__ float g_ao[MTOT * ODIM];                 // [m][h*64+d]

// ---------------------------------------------------------------------------
// Kernel 1: QKV projection.  out[m,o] = sum_c x[b,c,n]*w[c,o] + bias[o]
// A is read transposed directly from x (coalesced along m=n).
// Epilogue scatters into per-head Q/K/V.
// ---------------------------------------------------------------------------
#define BM 128
#define BN 128
#define BK 16

__global__ __launch_bounds__(256)
void gemm_qkv_kernel(const float* __restrict__ x,
                     const float* __restrict__ w,
                     const float* __restrict__ bias)
{
    __shared__ float As[BK][BM];
    __shared__ float Bs[BK][BN];

    const int tid = threadIdx.x;
    const int tm  = tid >> 4;     // 0..15
    const int tn  = tid & 15;     // 0..15
    const int m0  = blockIdx.y * BM;
    const int o0  = blockIdx.x * BN;

    const int b  = m0 >> 10;           // tile never crosses batch (1024 % 128 == 0)
    const int n0 = m0 & 1023;
    const float* Abase = x + b * CDIM * NTOK + n0;   // A[m][k] = Abase[k*NTOK + m]

    float acc[8][8];
#pragma unroll
    for (int i = 0; i < 8; i++)
#pragma unroll
        for (int j = 0; j < 8; j++) acc[i][j] = 0.f;

    for (int k0 = 0; k0 < CDIM; k0 += BK) {
#pragma unroll
        for (int i = 0; i < 8; i++) {
            int idx = tid + i * 256;
            int kk = idx >> 7, mm = idx & 127;
            As[kk][mm] = Abase[(k0 + kk) * NTOK + mm];
        }
#pragma unroll
        for (int i = 0; i < 8; i++) {
            int idx = tid + i * 256;
            int kk = idx >> 7, oo = idx & 127;
            Bs[kk][oo] = w[(k0 + kk) * QKVOUT + o0 + oo];
        }
        __syncthreads();

#pragma unroll
        for (int kk = 0; kk < BK; kk++) {
            float a[8], bb[8];
#pragma unroll
            for (int i = 0; i < 8; i++) a[i]  = As[kk][tm * 8 + i];
#pragma unroll
            for (int j = 0; j < 8; j++) bb[j] = Bs[kk][tn * 8 + j];
#pragma unroll
            for (int i = 0; i < 8; i++)
#pragma unroll
                for (int j = 0; j < 8; j++) acc[i][j] += a[i] * bb[j];
        }
        __syncthreads();
    }

    // scatter epilogue
#pragma unroll
    for (int j = 0; j < 8; j++) {
        const int o    = o0 + tn * 8 + j;
        const int head = o / (3 * DK);
        const int r    = o % (3 * DK);
        const int d    = r & (DK - 1);
        float* dst = (r < DK) ? g_q : (r < 2 * DK) ? g_k : g_v;
        const float bo = bias[o];
#pragma unroll
        for (int i = 0; i < 8; i++) {
            const int m = m0 + tm * 8 + i;
            const int n = m & 1023;
            const int bb2 = m >> 10;
            dst[(((bb2 * NHEADS + head) << 10) + n) * DK + d] = acc[i][j] + bo;
        }
    }
}

// ---------------------------------------------------------------------------
// Kernel 2: flash-style attention.
// Block: 256 threads (8 warps), 64 queries per block (8 per warp).
// Streams K/V in 64-key tiles, online softmax, O in registers.
// ---------------------------------------------------------------------------
#define QT 64
#define KT 64
#define SM_QS 0                          // 64*64
#define SM_KS (64 * 64)                  // 64*65 (padded: lane-varying row reads)
#define SM_VS (64 * 64 + 64 * 65)        // 64*64
#define ATTN_SMEM_BYTES ((64 * 64 + 64 * 65 + 64 * 64) * 4)

__global__ __launch_bounds__(256)
void attn_kernel()
{
    extern __shared__ float sm[];
    float* Qs = sm + SM_QS;   // [64][64]
    float* Ks = sm + SM_KS;   // [64][65]
    float* Vs = sm + SM_VS;   // [64][64]

    const int b  = blockIdx.z;
    const int h  = blockIdx.y;
    const int q0 = blockIdx.x * QT;

    const int tid  = threadIdx.x;
    const int warp = tid >> 5;
    const int lane = tid & 31;
    const int qb   = warp * 8;           // this warp's local query base

    const int   headOff = (b * NHEADS + h) * NTOK * DK;
    const float* Qg = g_q + headOff;
    const float* Kg = g_k + headOff;
    const float* Vg = g_v + headOff;
    const float scale = 0.125f;          // 1/sqrt(64)

    // load Q tile
#pragma unroll
    for (int i = 0; i < 16; i++) {
        int idx = tid + i * 256;
        int row = idx >> 6, col = idx & 63;
        Qs[row * 64 + col] = Qg[(q0 + row) * DK + col];
    }

    float o0a[8], o1a[8], mq[8], lq[8];
#pragma unroll
    for (int q = 0; q < 8; q++) { o0a[q] = 0.f; o1a[q] = 0.f; mq[q] = -1e30f; lq[q] = 0.f; }

    for (int kt = 0; kt < NTOK / KT; kt++) {
        __syncthreads();                 // protect previous tile's reads
#pragma unroll
        for (int i = 0; i < 16; i++) {
            int idx = tid + i * 256;
            int row = idx >> 6, col = idx & 63;
            int gk = (kt * KT + row) * DK + col;
            Ks[row * 65 + col] = Kg[gk];
            Vs[row * 64 + col] = Vg[gk];
        }
        __syncthreads();

        // ---- scores: 8 queries x 2 keys/lane ----
        float s0[8], s1[8];
#pragma unroll
        for (int q = 0; q < 8; q++) { s0[q] = 0.f; s1[q] = 0.f; }

#pragma unroll 4
        for (int d = 0; d < DK; d++) {
            float k0v = Ks[lane * 65 + d];
            float k1v = Ks[(lane + 32) * 65 + d];
#pragma unroll
            for (int q = 0; q < 8; q++) {
                float qd = Qs[(qb + q) * 64 + d];
                s0[q] += qd * k0v;
                s1[q] += qd * k1v;
            }
        }

        // ---- online softmax update ----
        float p0a[8], p1a[8];
#pragma unroll
        for (int q = 0; q < 8; q++) {
            s0[q] *= scale; s1[q] *= scale;
            float t = fmaxf(s0[q], s1[q]);
#pragma unroll
            for (int off = 16; off > 0; off >>= 1)
                t = fmaxf(t, __shfl_xor_sync(0xffffffffu, t, off));
            float mnew = fmaxf(mq[q], t);
            float p0 = __expf(s0[q] - mnew);
            float p1 = __expf(s1[q] - mnew);
            float corr = __expf(mq[q] - mnew);
            float ps = p0 + p1;
#pragma unroll
            for (int off = 16; off > 0; off >>= 1)
                ps += __shfl_xor_sync(0xffffffffu, ps, off);
            lq[q] = lq[q] * corr + ps;
            mq[q] = mnew;
            o0a[q] *= corr; o1a[q] *= corr;
            p0a[q] = p0; p1a[q] = p1;
        }

        // ---- O += P @ V  (broadcast p via shfl) ----
#pragma unroll 4
        for (int k = 0; k < 32; k++) {
            float v0 = Vs[k * 64 + lane];
            float v1 = Vs[k * 64 + lane + 32];
#pragma unroll
            for (int q = 0; q < 8; q++) {
                float pk = __shfl_sync(0xffffffffu, p0a[q], k);
                o0a[q] += pk * v0;
                o1a[q] += pk * v1;
            }
        }
#pragma unroll 4
        for (int k = 0; k < 32; k++) {
            float v0 = Vs[(k + 32) * 64 + lane];
            float v1 = Vs[(k + 32) * 64 + lane + 32];
#pragma unroll
            for (int q = 0; q < 8; q++) {
                float pk = __shfl_sync(0xffffffffu, p1a[q], k);
                o0a[q] += pk * v0;
                o1a[q] += pk * v1;
            }
        }
    }

    // ---- finalize + write [m][h*64+d] ----
#pragma unroll
    for (int q = 0; q < 8; q++) {
        float inv = 1.f / lq[q];
        int qg = q0 + qb + q;
        float* dst = g_ao + ((b << 10) + qg) * ODIM + (h << 6);
        dst[lane]      = o0a[q] * inv;
        dst[lane + 32] = o1a[q] * inv;
    }
}

// ---------------------------------------------------------------------------
// Kernel 3: output projection + bias + residual + transpose back to NCHW.
// ---------------------------------------------------------------------------
__global__ __launch_bounds__(256)
void gemm_out_kernel(const float* __restrict__ w,
                     const float* __restrict__ bias,
                     const float* __restrict__ x,
                     float* __restrict__ out)
{
    __shared__ float As[BK][BM + 4];
    __shared__ float Bs[BK][BN];

    const int tid = threadIdx.x;
    const int tm  = tid >> 4;
    const int tn  = tid & 15;
    const int m0  = blockIdx.y * BM;
    const int o0  = blockIdx.x * BN;

    float acc[8][8];
#pragma unroll
    for (int i = 0; i < 8; i++)
#pragma unroll
        for (int j = 0; j < 8; j++) acc[i][j] = 0.f;

    for (int k0 = 0; k0 < ODIM; k0 += BK) {
        // A[m][k] = g_ao[m*512+k]: load k-fastest for coalescing
#pragma unroll
        for (int i = 0; i < 8; i++) {
            int idx = tid + i * 256;
            int kk = idx & 15, mm = idx >> 4;
            As[kk][mm] = g_ao[(m0 + mm) * ODIM + k0 + kk];
        }
#pragma unroll
        for (int i = 0; i < 8; i++) {
            int idx = tid + i * 256;
            int kk = idx >> 7, oo = idx & 127;
            Bs[kk][oo] = w[(k0 + kk) * CDIM + o0 + oo];
        }
        __syncthreads();

#pragma unroll
        for (int kk = 0; kk < BK; kk++) {
            float a[8], bb[8];
#pragma unroll
            for (int i = 0; i < 8; i++) a[i]  = As[kk][tm * 8 + i];
#pragma unroll
            for (int j = 0; j < 8; j++) bb[j] = Bs[kk][tn * 8 + j];
#pragma unroll
            for (int i = 0; i < 8; i++)
#pragma unroll
                for (int j = 0; j < 8; j++) acc[i][j] += a[i] * bb[j];
        }
        __syncthreads();
    }

    // epilogue: + bias + residual xs[m][o], store transposed out[b,o,n]
    const int b     = m0 >> 10;
    const int nbase = (m0 & 1023) + tm * 8;
#pragma unroll
    for (int j = 0; j < 8; j++) {
        const int o  = o0 + tn * 8 + j;
        const float bo = bias[o];
        const int base = ((b * CDIM + o) << 10) + nbase;
        float4 r0 = *reinterpret_cast<const float4*>(&x[base]);
        float4 r1 = *reinterpret_cast<const float4*>(&x[base + 4]);
        float4 v0 = make_float4(acc[0][j] + bo + r0.x, acc[1][j] + bo + r0.y,
                                acc[2][j] + bo + r0.z, acc[3][j] + bo + r0.w);
        float4 v1 = make_float4(acc[4][j] + bo + r1.x, acc[5][j] + bo + r1.y,
                                acc[6][j] + bo + r1.z, acc[7][j] + bo + r1.w);
        *reinterpret_cast<float4*>(&out[base])     = v0;
        *reinterpret_cast<float4*>(&out[base + 4]) = v1;
    }
}

// ---------------------------------------------------------------------------
// Launch
// ---------------------------------------------------------------------------
extern "C" void kernel_launch(void* const* d_in, const int* in_sizes, int n_in,
                              void* d_out, int out_size)
{
    const float* x      = (const float*)d_in[0];
    const float* w_proj = (const float*)d_in[1];
    const float* b_proj = (const float*)d_in[2];
    const float* w_out  = (const float*)d_in[3];
    const float* b_out  = (const float*)d_in[4];
    float* out = (float*)d_out;

    cudaFuncSetAttribute(attn_kernel,
                         cudaFuncAttributeMaxDynamicSharedMemorySize,
                         ATTN_SMEM_BYTES);

    gemm_qkv_kernel<<<dim3(QKVOUT / BN, MTOT / BM), 256>>>(x, w_proj, b_proj);
    attn_kernel<<<dim3(NTOK / QT, NHEADS, BATCH), 256, ATTN_SMEM_BYTES>>>();
    gemm_out_kernel<<<dim3(CDIM / BN, MTOT / BM), 256>>>(w_out, b_out, x, out);
}

// round 3
// speedup vs baseline: 1.0014x; 1.0014x over previous
#include <cuda_runtime.h>
#include <math.h>

// ---------------------------------------------------------------------------
// Problem constants
// ---------------------------------------------------------------------------
#define BATCH   16
#define CDIM    512
#define NTOK    1024          // H*W = 32*32
#define NHEADS  8
#define DK      64
#define MTOT    (BATCH * NTOK)        // 16384
#define QKVOUT  (NHEADS * DK * 3)     // 1536
#define ODIM    (NHEADS * DK)         // 512

// ---------------------------------------------------------------------------
// Scratch (device globals; no runtime allocation allowed)
// ---------------------------------------------------------------------------
__device__ float g_q[BATCH * NHEADS * NTOK * DK];   // [b,h,n,d]
__device__ float g_k[BATCH * NHEADS * NTOK * DK];
__device__ float g_v[BATCH * NHEADS * NTOK * DK];
__device__ float g_ao[MTOT * ODIM];                 // [m][h*64+d]

// ---------------------------------------------------------------------------
// Kernel 1: QKV projection.  out[m,o] = sum_c x[b,c,n]*w[c,o] + bias[o]
// A is read transposed directly from x (coalesced along m=n).
// Epilogue scatters into per-head Q/K/V.
// ---------------------------------------------------------------------------
#define BM 128
#define BN 128
#define BK 16

__global__ __launch_bounds__(256)
void gemm_qkv_kernel(const float* __restrict__ x,
                     const float* __restrict__ w,
                     const float* __restrict__ bias)
{
    __shared__ float As[BK][BM];
    __shared__ float Bs[BK][BN];

    const int tid = threadIdx.x;
    const int tm  = tid >> 4;     // 0..15
    const int tn  = tid & 15;     // 0..15
    const int m0  = blockIdx.y * BM;
    const int o0  = blockIdx.x * BN;

    const int b  = m0 >> 10;           // tile never crosses batch (1024 % 128 == 0)
    const int n0 = m0 & 1023;
    const float* Abase = x + b * CDIM * NTOK + n0;   // A[m][k] = Abase[k*NTOK + m]

    float acc[8][8];
#pragma unroll
    for (int i = 0; i < 8; i++)
#pragma unroll
        for (int j = 0; j < 8; j++) acc[i][j] = 0.f;

    for (int k0 = 0; k0 < CDIM; k0 += BK) {
#pragma unroll
        for (int i = 0; i < 8; i++) {
            int idx = tid + i * 256;
            int kk = idx >> 7, mm = idx & 127;
            As[kk][mm] = Abase[(k0 + kk) * NTOK + mm];
        }
#pragma unroll
        for (int i = 0; i < 8; i++) {
            int idx = tid + i * 256;
            int kk = idx >> 7, oo = idx & 127;
            Bs[kk][oo] = w[(k0 + kk) * QKVOUT + o0 + oo];
        }
        __syncthreads();

#pragma unroll
        for (int kk = 0; kk < BK; kk++) {
            float a[8], bb[8];
#pragma unroll
            for (int i = 0; i < 8; i++) a[i]  = As[kk][tm * 8 + i];
#pragma unroll
            for (int j = 0; j < 8; j++) bb[j] = Bs[kk][tn * 8 + j];
#pragma unroll
            for (int i = 0; i < 8; i++)
#pragma unroll
                for (int j = 0; j < 8; j++) acc[i][j] += a[i] * bb[j];
        }
        __syncthreads();
    }

    // scatter epilogue
#pragma unroll
    for (int j = 0; j < 8; j++) {
        const int o    = o0 + tn * 8 + j;
        const int head = o / (3 * DK);
        const int r    = o % (3 * DK);
        const int d    = r & (DK - 1);
        float* dst = (r < DK) ? g_q : (r < 2 * DK) ? g_k : g_v;
        const float bo = bias[o];
#pragma unroll
        for (int i = 0; i < 8; i++) {
            const int m = m0 + tm * 8 + i;
            const int n = m & 1023;
            const int bb2 = m >> 10;
            dst[(((bb2 * NHEADS + head) << 10) + n) * DK + d] = acc[i][j] + bo;
        }
    }
}

// ---------------------------------------------------------------------------
// Kernel 2: flash-style attention.
// Block: 256 threads (8 warps), 64 queries per block (8 per warp).
// Streams K/V in 64-key tiles, online softmax, O in registers.
// ---------------------------------------------------------------------------
#define QT 64
#define KT 64
#define SM_QS 0                          // 64*64
#define SM_KS (64 * 64)                  // 64*65 (padded: lane-varying row reads)
#define SM_VS (64 * 64 + 64 * 65)        // 64*64
#define ATTN_SMEM_BYTES ((64 * 64 + 64 * 65 + 64 * 64) * 4)

__global__ __launch_bounds__(256)
void attn_kernel()
{
    extern __shared__ float sm[];
    float* Qs = sm + SM_QS;   // [64][64]
    float* Ks = sm + SM_KS;   // [64][65]
    float* Vs = sm + SM_VS;   // [64][64]

    const int b  = blockIdx.z;
    const int h  = blockIdx.y;
    const int q0 = blockIdx.x * QT;

    const int tid  = threadIdx.x;
    const int warp = tid >> 5;
    const int lane = tid & 31;
    const int qb   = warp * 8;           // this warp's local query base

    const int   headOff = (b * NHEADS + h) * NTOK * DK;
    const float* Qg = g_q + headOff;
    const float* Kg = g_k + headOff;
    const float* Vg = g_v + headOff;
    const float scale = 0.125f;          // 1/sqrt(64)

    // load Q tile
#pragma unroll
    for (int i = 0; i < 16; i++) {
        int idx = tid + i * 256;
        int row = idx >> 6, col = idx & 63;
        Qs[row * 64 + col] = Qg[(q0 + row) * DK + col];
    }

    float o0a[8], o1a[8], mq[8], lq[8];
#pragma unroll
    for (int q = 0; q < 8; q++) { o0a[q] = 0.f; o1a[q] = 0.f; mq[q] = -1e30f; lq[q] = 0.f; }

    for (int kt = 0; kt < NTOK / KT; kt++) {
        __syncthreads();                 // protect previous tile's reads
#pragma unroll
        for (int i = 0; i < 16; i++) {
            int idx = tid + i * 256;
            int row = idx >> 6, col = idx & 63;
            int gk = (kt * KT + row) * DK + col;
            Ks[row * 65 + col] = Kg[gk];
            Vs[row * 64 + col] = Vg[gk];
        }
        __syncthreads();

        // ---- scores: 8 queries x 2 keys/lane ----
        float s0[8], s1[8];
#pragma unroll
        for (int q = 0; q < 8; q++) { s0[q] = 0.f; s1[q] = 0.f; }

#pragma unroll 4
        for (int d = 0; d < DK; d++) {
            float k0v = Ks[lane * 65 + d];
            float k1v = Ks[(lane + 32) * 65 + d];
#pragma unroll
            for (int q = 0; q < 8; q++) {
                float qd = Qs[(qb + q) * 64 + d];
                s0[q] += qd * k0v;
                s1[q] += qd * k1v;
            }
        }

        // ---- online softmax update ----
        float p0a[8], p1a[8];
#pragma unroll
        for (int q = 0; q < 8; q++) {
            s0[q] *= scale; s1[q] *= scale;
            float t = fmaxf(s0[q], s1[q]);
#pragma unroll
            for (int off = 16; off > 0; off >>= 1)
                t = fmaxf(t, __shfl_xor_sync(0xffffffffu, t, off));
            float mnew = fmaxf(mq[q], t);
            float p0 = __expf(s0[q] - mnew);
            float p1 = __expf(s1[q] - mnew);
            float corr = __expf(mq[q] - mnew);
            float ps = p0 + p1;
#pragma unroll
            for (int off = 16; off > 0; off >>= 1)
                ps += __shfl_xor_sync(0xffffffffu, ps, off);
            lq[q] = lq[q] * corr + ps;
            mq[q] = mnew;
            o0a[q] *= corr; o1a[q] *= corr;
            p0a[q] = p0; p1a[q] = p1;
        }

        // ---- O += P @ V  (broadcast p via shfl) ----
#pragma unroll 4
        for (int k = 0; k < 32; k++) {
            float v0 = Vs[k * 64 + lane];
            float v1 = Vs[k * 64 + lane + 32];
#pragma unroll
            for (int q = 0; q < 8; q++) {
                float pk = __shfl_sync(0xffffffffu, p0a[q], k);
                o0a[q] += pk * v0;
                o1a[q] += pk * v1;
            }
        }
#pragma unroll 4
        for (int k = 0; k < 32; k++) {
            float v0 = Vs[(k + 32) * 64 + lane];
            float v1 = Vs[(k + 32) * 64 + lane + 32];
#pragma unroll
            for (int q = 0; q < 8; q++) {
                float pk = __shfl_sync(0xffffffffu, p1a[q], k);
                o0a[q] += pk * v0;
                o1a[q] += pk * v1;
            }
        }
    }

    // ---- finalize + write [m][h*64+d] ----
#pragma unroll
    for (int q = 0; q < 8; q++) {
        float inv = 1.f / lq[q];
        int qg = q0 + qb + q;
        float* dst = g_ao + ((b << 10) + qg) * ODIM + (h << 6);
        dst[lane]      = o0a[q] * inv;
        dst[lane + 32] = o1a[q] * inv;
    }
}

// ---------------------------------------------------------------------------
// Kernel 3: output projection + bias + residual + transpose back to NCHW.
// ---------------------------------------------------------------------------
__global__ __launch_bounds__(256)
void gemm_out_kernel(const float* __restrict__ w,
                     const float* __restrict__ bias,
                     const float* __restrict__ x,
                     float* __restrict__ out)
{
    __shared__ float As[BK][BM + 4];
    __shared__ float Bs[BK][BN];

    const int tid = threadIdx.x;
    const int tm  = tid >> 4;
    const int tn  = tid & 15;
    const int m0  = blockIdx.y * BM;
    const int o0  = blockIdx.x * BN;

    float acc[8][8];
#pragma unroll
    for (int i = 0; i < 8; i++)
#pragma unroll
        for (int j = 0; j < 8; j++) acc[i][j] = 0.f;

    for (int k0 = 0; k0 < ODIM; k0 += BK) {
        // A[m][k] = g_ao[m*512+k]: load k-fastest for coalescing
#pragma unroll
        for (int i = 0; i < 8; i++) {
            int idx = tid + i * 256;
            int kk = idx & 15, mm = idx >> 4;
            As[kk][mm] = g_ao[(m0 + mm) * ODIM + k0 + kk];
        }
#pragma unroll
        for (int i = 0; i < 8; i++) {
            int idx = tid + i * 256;
            int kk = idx >> 7, oo = idx & 127;
            Bs[kk][oo] = w[(k0 + kk) * CDIM + o0 + oo];
        }
        __syncthreads();

#pragma unroll
        for (int kk = 0; kk < BK; kk++) {
            float a[8], bb[8];
#pragma unroll
            for (int i = 0; i < 8; i++) a[i]  = As[kk][tm * 8 + i];
#pragma unroll
            for (int j = 0; j < 8; j++) bb[j] = Bs[kk][tn * 8 + j];
#pragma unroll
            for (int i = 0; i < 8; i++)
#pragma unroll
                for (int j = 0; j < 8; j++) acc[i][j] += a[i] * bb[j];
        }
        __syncthreads();
    }

    // epilogue: + bias + residual xs[m][o], store transposed out[b,o,n]
    const int b     = m0 >> 10;
    const int nbase = (m0 & 1023) + tm * 8;
#pragma unroll
    for (int j = 0; j < 8; j++) {
        const int o  = o0 + tn * 8 + j;
        const float bo = bias[o];
        const int base = ((b * CDIM + o) << 10) + nbase;
        float4 r0 = *reinterpret_cast<const float4*>(&x[base]);
        float4 r1 = *reinterpret_cast<const float4*>(&x[base + 4]);
        float4 v0 = make_float4(acc[0][j] + bo + r0.x, acc[1][j] + bo + r0.y,
                                acc[2][j] + bo + r0.z, acc[3][j] + bo + r0.w);
        float4 v1 = make_float4(acc[4][j] + bo + r1.x, acc[5][j] + bo + r1.y,
                                acc[6][j] + bo + r1.z, acc[7][j] + bo + r1.w);
        *reinterpret_cast<float4*>(&out[base])     = v0;
        *reinterpret_cast<float4*>(&out[base + 4]) = v1;
    }
}

// ---------------------------------------------------------------------------
// Launch
// ---------------------------------------------------------------------------
extern "C" void kernel_launch(void* const* d_in, const int* in_sizes, int n_in,
                              void* d_out, int out_size)
{
    const float* x      = (const float*)d_in[0];
    const float* w_proj = (const float*)d_in[1];
    const float* b_proj = (const float*)d_in[2];
    const float* w_out  = (const float*)d_in[3];
    const float* b_out  = (const float*)d_in[4];
    float* out = (float*)d_out;

    cudaFuncSetAttribute(attn_kernel,
                         cudaFuncAttributeMaxDynamicSharedMemorySize,
                         ATTN_SMEM_BYTES);

    gemm_qkv_kernel<<<dim3(QKVOUT / BN, MTOT / BM), 256>>>(x, w_proj, b_proj);
    attn_kernel<<<dim3(NTOK / QT, NHEADS, BATCH), 256, ATTN_SMEM_BYTES>>>();
    gemm_out_kernel<<<dim3(CDIM / BN, MTOT / BM), 256>>>(w_out, b_out, x, out);
}

// round 5
// speedup vs baseline: 2.2802x; 2.2769x over previous
#include <cuda_runtime.h>
#include <cuda_bf16.h>
#include <cstdint>

#define NTOK 1024
#define QKVOUT 1536

typedef __nv_bfloat16 bf;
typedef __nv_bfloat162 bf2;

__device__ float g_q [16*8*NTOK*64];   // [bh][n][d]
__device__ float g_k [16*8*NTOK*64];   // [bh][n][d]
__device__ float g_vT[16*8*64*NTOK];   // [bh][d][n]
__device__ float g_ao[16*NTOK*512];    // [m][h*64+d]

__device__ __forceinline__ void bsplit(float v, bf& h, bf& l) {
    h = __float2bfloat16(v);
    l = __float2bfloat16(v - __bfloat162float(h));
}
__device__ __forceinline__ void mma_bf(float* c, const uint32_t* a,
                                       uint32_t b0, uint32_t b1) {
    asm volatile(
        "mma.sync.aligned.m16n8k16.row.col.f32.bf16.bf16.f32 "
        "{%0,%1,%2,%3}, {%4,%5,%6,%7}, {%8,%9}, {%0,%1,%2,%3};"
        : "+f"(c[0]), "+f"(c[1]), "+f"(c[2]), "+f"(c[3])
        : "r"(a[0]), "r"(a[1]), "r"(a[2]), "r"(a[3]), "r"(b0), "r"(b1));
}
__device__ __forceinline__ uint32_t ldu32(const bf* p) {
    return *(const uint32_t*)p;
}

// ============ Kernel 1: QKV projection (bf16x3 mma.sync) ====================
// smem: AH 0 | AL 10240B | BH 20480 | BL 30720 ; epilogue stage f32[128][130]
#define GEMM_SMEM 66560

__global__ __launch_bounds__(256)
void gemm_qkv(const float* __restrict__ x, const float* __restrict__ w,
              const float* __restrict__ bias)
{
    extern __shared__ char sm[];
    bf* AH = (bf*)sm;            bf* AL = AH + 128*40;
    bf* BH = AL + 128*40;        bf* BL = BH + 128*40;

    const int tid = threadIdx.x, wid = tid >> 5, lane = tid & 31;
    const int g = lane >> 2, tg = lane & 3;
    const int wm = wid & 3, wn = wid >> 2;
    const int m0 = blockIdx.y * 128, o0 = blockIdx.x * 128;
    const int b = m0 >> 10, n0 = m0 & 1023;
    const float* Ab = x + b * 512 * NTOK + n0;

    float acc[2][8][4];
#pragma unroll
    for (int i = 0; i < 2; i++)
#pragma unroll
        for (int j = 0; j < 8; j++)
#pragma unroll
            for (int q = 0; q < 4; q++) acc[i][j][q] = 0.f;

    for (int ck = 0; ck < 16; ck++) {
        __syncthreads();
#pragma unroll
        for (int it = 0; it < 8; it++) {              // A 128m x 32k
            int idx = tid + it * 256; int m = idx & 127, k2 = idx >> 7;
            float v0 = Ab[(ck * 32 + 2 * k2) * NTOK + m];
            float v1 = Ab[(ck * 32 + 2 * k2 + 1) * NTOK + m];
            bf h0, l0, h1, l1; bsplit(v0, h0, l0); bsplit(v1, h1, l1);
            bf2 ph; ph.x = h0; ph.y = h1;
            bf2 pl; pl.x = l0; pl.y = l1;
            *(bf2*)(AH + m * 40 + 2 * k2) = ph;
            *(bf2*)(AL + m * 40 + 2 * k2) = pl;
        }
#pragma unroll
        for (int it = 0; it < 8; it++) {              // B 128o x 32k
            int idx = tid + it * 256; int oo = idx & 127, k2 = idx >> 7;
            float v0 = w[(ck * 32 + 2 * k2) * QKVOUT + o0 + oo];
            float v1 = w[(ck * 32 + 2 * k2 + 1) * QKVOUT + o0 + oo];
            bf h0, l0, h1, l1; bsplit(v0, h0, l0); bsplit(v1, h1, l1);
            bf2 ph; ph.x = h0; ph.y = h1;
            bf2 pl; pl.x = l0; pl.y = l1;
            *(bf2*)(BH + oo * 40 + 2 * k2) = ph;
            *(bf2*)(BL + oo * 40 + 2 * k2) = pl;
        }
        __syncthreads();
#pragma unroll
        for (int ks = 0; ks < 2; ks++) {
            const int kb = ks * 16;
            uint32_t ah[2][4], al[2][4];
#pragma unroll
            for (int mt = 0; mt < 2; mt++) {
                int rb = wm * 32 + mt * 16;
                ah[mt][0] = ldu32(AH + (rb + g) * 40 + kb + 2 * tg);
                ah[mt][1] = ldu32(AH + (rb + g + 8) * 40 + kb + 2 * tg);
                ah[mt][2] = ldu32(AH + (rb + g) * 40 + kb + 2 * tg + 8);
                ah[mt][3] = ldu32(AH + (rb + g + 8) * 40 + kb + 2 * tg + 8);
                al[mt][0] = ldu32(AL + (rb + g) * 40 + kb + 2 * tg);
                al[mt][1] = ldu32(AL + (rb + g + 8) * 40 + kb + 2 * tg);
                al[mt][2] = ldu32(AL + (rb + g) * 40 + kb + 2 * tg + 8);
                al[mt][3] = ldu32(AL + (rb + g + 8) * 40 + kb + 2 * tg + 8);
            }
#pragma unroll
            for (int nt = 0; nt < 8; nt++) {
                int nb = wn * 64 + nt * 8 + g;
                uint32_t bh0 = ldu32(BH + nb * 40 + kb + 2 * tg);
                uint32_t bh1 = ldu32(BH + nb * 40 + kb + 2 * tg + 8);
                uint32_t bl0 = ldu32(BL + nb * 40 + kb + 2 * tg);
                uint32_t bl1 = ldu32(BL + nb * 40 + kb + 2 * tg + 8);
#pragma unroll
                for (int mt = 0; mt < 2; mt++) {
                    mma_bf(acc[mt][nt], ah[mt], bh0, bh1);
                    mma_bf(acc[mt][nt], ah[mt], bl0, bl1);
                    mma_bf(acc[mt][nt], al[mt], bh0, bh1);
                }
            }
        }
    }
    __syncthreads();
    float* stg = (float*)sm;                          // [128][130]
#pragma unroll
    for (int mt = 0; mt < 2; mt++)
#pragma unroll
        for (int nt = 0; nt < 8; nt++) {
            int r0 = wm * 32 + mt * 16 + g, c = wn * 64 + nt * 8 + 2 * tg;
            stg[r0 * 130 + c]       = acc[mt][nt][0];
            stg[r0 * 130 + c + 1]   = acc[mt][nt][1];
            stg[(r0 + 8) * 130 + c]     = acc[mt][nt][2];
            stg[(r0 + 8) * 130 + c + 1] = acc[mt][nt][3];
        }
    __syncthreads();
    for (int j = 0; j < 64; j++) {                    // q,k: lanes vary o
        int idx = tid + j * 256; int oc = idx & 127, rr = idx >> 7;
        int o = o0 + oc, head = o / 192, r2 = o - head * 192;
        if (r2 < 128) {
            float val = stg[rr * 130 + oc] + bias[o];
            float* dst = (r2 < 64) ? g_q : g_k;
            dst[(((b * 8 + head) << 10) + n0 + rr) * 64 + (r2 & 63)] = val;
        }
    }
    for (int j = 0; j < 64; j++) {                    // vT: lanes vary n
        int idx = tid + j * 256; int rr = idx & 127, oc = idx >> 7;
        int o = o0 + oc, head = o / 192, r2 = o - head * 192;
        if (r2 >= 128)
            g_vT[((b * 8 + head) * 64 + (r2 - 128)) * 1024 + n0 + rr] =
                stg[rr * 130 + oc] + bias[o];
    }
}

// ============ Kernel 2: attention (bf16x3 mma.sync flash) ===================
// bytes: QH 0 QL 18432 KH 36864 KL 46080 VH 55296 VL 64512 SS 73728(f32 128x68)
//        PH 108544 PL 126976 ; total 145408
#define ATTN_SMEM 145408

__global__ __launch_bounds__(256)
void attn_kernel()
{
    extern __shared__ char sm[];
    bf* QH = (bf*)sm;              bf* QL = QH + 128*72;
    bf* KH = QL + 128*72;          bf* KL = KH + 64*72;
    bf* VH = KL + 64*72;           bf* VL = VH + 64*72;
    float* SS = (float*)(sm + 73728);                 // [128][68]
    bf* PH = (bf*)(sm + 108544);   bf* PL = PH + 128*72;
    __shared__ float m_row[128], l_row[128], corr_row[128];

    const int tid = threadIdx.x, wid = tid >> 5, lane = tid & 31;
    const int g = lane >> 2, tg = lane & 3;
    const int wm = wid & 3, wn = wid >> 2;
    const int bh = blockIdx.y, q0 = blockIdx.x * 128;
    const float* Qg = g_q  + bh * (NTOK * 64);
    const float* Kg = g_k  + bh * (NTOK * 64);
    const float* Vg = g_vT + bh * (64 * NTOK);

    if (tid < 128) { m_row[tid] = -1e30f; l_row[tid] = 0.f; }

#pragma unroll 4
    for (int it = 0; it < 16; it++) {                 // Q 128x64, scale folded
        int idx = tid + it * 256; int d2 = idx & 31, q = idx >> 5;
        float2 qv = *(const float2*)&Qg[(q0 + q) * 64 + 2 * d2];
        bf h0, l0, h1, l1;
        bsplit(qv.x * 0.125f, h0, l0); bsplit(qv.y * 0.125f, h1, l1);
        bf2 ph; ph.x = h0; ph.y = h1;
        bf2 pl; pl.x = l0; pl.y = l1;
        *(bf2*)(QH + q * 72 + 2 * d2) = ph;
        *(bf2*)(QL + q * 72 + 2 * d2) = pl;
    }
    float o[2][4][4];
#pragma unroll
    for (int i = 0; i < 2; i++)
#pragma unroll
        for (int j = 0; j < 4; j++)
#pragma unroll
            for (int q = 0; q < 4; q++) o[i][j][q] = 0.f;

    for (int t = 0; t < 16; t++) {
        __syncthreads();
#pragma unroll
        for (int it = 0; it < 8; it++) {              // K 64x64
            int idx = tid + it * 256; int d2 = idx & 31, r = idx >> 5;
            float2 kv = *(const float2*)&Kg[(t * 64 + r) * 64 + 2 * d2];
            bf h0, l0, h1, l1; bsplit(kv.x, h0, l0); bsplit(kv.y, h1, l1);
            bf2 ph; ph.x = h0; ph.y = h1;
            bf2 pl; pl.x = l0; pl.y = l1;
            *(bf2*)(KH + r * 72 + 2 * d2) = ph;
            *(bf2*)(KL + r * 72 + 2 * d2) = pl;
        }
#pragma unroll
        for (int it = 0; it < 8; it++) {              // V [d][key] 64x64
            int idx = tid + it * 256; int k2 = idx & 31, d = idx >> 5;
            float2 vv = *(const float2*)&Vg[d * 1024 + t * 64 + 2 * k2];
            bf h0, l0, h1, l1; bsplit(vv.x, h0, l0); bsplit(vv.y, h1, l1);
            bf2 ph; ph.x = h0; ph.y = h1;
            bf2 pl; pl.x = l0; pl.y = l1;
            *(bf2*)(VH + d * 72 + 2 * k2) = ph;
            *(bf2*)(VL + d * 72 + 2 * k2) = pl;
        }
        __syncthreads();
        float s[2][4][4];                             // S = Q K^T
#pragma unroll
        for (int i = 0; i < 2; i++)
#pragma unroll
            for (int j = 0; j < 4; j++)
#pragma unroll
                for (int q = 0; q < 4; q++) s[i][j][q] = 0.f;
#pragma unroll
        for (int ks = 0; ks < 4; ks++) {
            const int kb = ks * 16;
            uint32_t ah[2][4], al[2][4];
#pragma unroll
            for (int mt = 0; mt < 2; mt++) {
                int rb = wm * 32 + mt * 16;
                ah[mt][0] = ldu32(QH + (rb + g) * 72 + kb + 2 * tg);
                ah[mt][1] = ldu32(QH + (rb + g + 8) * 72 + kb + 2 * tg);
                ah[mt][2] = ldu32(QH + (rb + g) * 72 + kb + 2 * tg + 8);
                ah[mt][3] = ldu32(QH + (rb + g + 8) * 72 + kb + 2 * tg + 8);
                al[mt][0] = ldu32(QL + (rb + g) * 72 + kb + 2 * tg);
                al[mt][1] = ldu32(QL + (rb + g + 8) * 72 + kb + 2 * tg);
                al[mt][2] = ldu32(QL + (rb + g) * 72 + kb + 2 * tg + 8);
                al[mt][3] = ldu32(QL + (rb + g + 8) * 72 + kb + 2 * tg + 8);
            }
#pragma unroll
            for (int nt = 0; nt < 4; nt++) {
                int nb = wn * 32 + nt * 8 + g;
                uint32_t bh0 = ldu32(KH + nb * 72 + kb + 2 * tg);
                uint32_t bh1 = ldu32(KH + nb * 72 + kb + 2 * tg + 8);
                uint32_t bl0 = ldu32(KL + nb * 72 + kb + 2 * tg);
                uint32_t bl1 = ldu32(KL + nb * 72 + kb + 2 * tg + 8);
#pragma unroll
                for (int mt = 0; mt < 2; mt++) {
                    mma_bf(s[mt][nt], ah[mt], bh0, bh1);
                    mma_bf(s[mt][nt], ah[mt], bl0, bl1);
                    mma_bf(s[mt][nt], al[mt], bh0, bh1);
                }
            }
        }
#pragma unroll
        for (int mt = 0; mt < 2; mt++)
#pragma unroll
            for (int nt = 0; nt < 4; nt++) {
                int r0 = wm * 32 + mt * 16 + g, c = wn * 32 + nt * 8 + 2 * tg;
                float2 v0; v0.x = s[mt][nt][0]; v0.y = s[mt][nt][1];
                float2 v1; v1.x = s[mt][nt][2]; v1.y = s[mt][nt][3];
                *(float2*)&SS[r0 * 68 + c] = v0;
                *(float2*)&SS[(r0 + 8) * 68 + c] = v1;
            }
        __syncthreads();
        {                                             // softmax: 2 thr/row
            int row = tid >> 1, half = tid & 1, cb = half * 32;
            float mo = m_row[row];
            float lm = -1e30f;
#pragma unroll 8
            for (int i = 0; i < 32; i++) lm = fmaxf(lm, SS[row * 68 + cb + i]);
            lm = fmaxf(lm, __shfl_xor_sync(0xffffffffu, lm, 1));
            float mn = fmaxf(mo, lm);
            float corr = __expf(mo - mn);
            float ps = 0.f;
#pragma unroll 8
            for (int i = 0; i < 32; i++) {
                float p = __expf(SS[row * 68 + cb + i] - mn);
                bf ph = __float2bfloat16(p);
                bf pl = __float2bfloat16(p - __bfloat162float(ph));
                PH[row * 72 + cb + i] = ph;
                PL[row * 72 + cb + i] = pl;
                ps += __bfloat162float(ph) + __bfloat162float(pl);
            }
            ps += __shfl_xor_sync(0xffffffffu, ps, 1);
            if (half == 0) {
                m_row[row] = mn;
                l_row[row] = l_row[row] * corr + ps;
                corr_row[row] = corr;
            }
        }
        __syncthreads();
#pragma unroll
        for (int mt = 0; mt < 2; mt++) {              // rescale O
            float c0 = corr_row[wm * 32 + mt * 16 + g];
            float c1 = corr_row[wm * 32 + mt * 16 + g + 8];
#pragma unroll
            for (int nt = 0; nt < 4; nt++) {
                o[mt][nt][0] *= c0; o[mt][nt][1] *= c0;
                o[mt][nt][2] *= c1; o[mt][nt][3] *= c1;
            }
        }
#pragma unroll
        for (int ks = 0; ks < 4; ks++) {              // O += P V
            const int kb = ks * 16;
            uint32_t ah[2][4], al[2][4];
#pragma unroll
            for (int mt = 0; mt < 2; mt++) {
                int rb = wm * 32 + mt * 16;
                ah[mt][0] = ldu32(PH + (rb + g) * 72 + kb + 2 * tg);
                ah[mt][1] = ldu32(PH + (rb + g + 8) * 72 + kb + 2 * tg);
                ah[mt][2] = ldu32(PH + (rb + g) * 72 + kb + 2 * tg + 8);
                ah[mt][3] = ldu32(PH + (rb + g + 8) * 72 + kb + 2 * tg + 8);
                al[mt][0] = ldu32(PL + (rb + g) * 72 + kb + 2 * tg);
                al[mt][1] = ldu32(PL + (rb + g + 8) * 72 + kb + 2 * tg);
                al[mt][2] = ldu32(PL + (rb + g) * 72 + kb + 2 * tg + 8);
                al[mt][3] = ldu32(PL + (rb + g + 8) * 72 + kb + 2 * tg + 8);
            }
#pragma unroll
            for (int nt = 0; nt < 4; nt++) {
                int nb = wn * 32 + nt * 8 + g;
                uint32_t bh0 = ldu32(VH + nb * 72 + kb + 2 * tg);
                uint32_t bh1 = ldu32(VH + nb * 72 + kb + 2 * tg + 8);
                uint32_t bl0 = ldu32(VL + nb * 72 + kb + 2 * tg);
                uint32_t bl1 = ldu32(VL + nb * 72 + kb + 2 * tg + 8);
#pragma unroll
                for (int mt = 0; mt < 2; mt++) {
                    mma_bf(o[mt][nt], ah[mt], bh0, bh1);
                    mma_bf(o[mt][nt], ah[mt], bl0, bl1);
                    mma_bf(o[mt][nt], al[mt], bh0, bh1);
                }
            }
        }
    }
    __syncthreads();
    float* ostg = SS;                                 // [128][65]
#pragma unroll
    for (int mt = 0; mt < 2; mt++) {
        int r0 = wm * 32 + mt * 16 + g;
        float i0 = 1.f / l_row[r0], i1 = 1.f / l_row[r0 + 8];
#pragma unroll
        for (int nt = 0; nt < 4; nt++) {
            int c = wn * 32 + nt * 8 + 2 * tg;
            ostg[r0 * 65 + c]       = o[mt][nt][0] * i0;
            ostg[r0 * 65 + c + 1]   = o[mt][nt][1] * i0;
            ostg[(r0 + 8) * 65 + c]     = o[mt][nt][2] * i1;
            ostg[(r0 + 8) * 65 + c + 1] = o[mt][nt][3] * i1;
        }
    }
    __syncthreads();
    const int b = bh >> 3, h = bh & 7;
    for (int j = 0; j < 32; j++) {
        int idx = tid + j * 256; int d = idx & 63, rr = idx >> 6;
        g_ao[((b << 10) + q0 + rr) * 512 + h * 64 + d] = ostg[rr * 65 + d];
    }
}

// ============ Kernel 3: out projection + bias + residual ====================
__global__ __launch_bounds__(256)
void gemm_out(const float* __restrict__ w, const float* __restrict__ bias,
              const float* __restrict__ x, float* __restrict__ out)
{
    extern __shared__ char sm[];
    bf* AH = (bf*)sm;            bf* AL = AH + 128*40;
    bf* BH = AL + 128*40;        bf* BL = BH + 128*40;

    const int tid = threadIdx.x, wid = tid >> 5, lane = tid & 31;
    const int g = lane >> 2, tg = lane & 3;
    const int wm = wid & 3, wn = wid >> 2;
    const int m0 = blockIdx.y * 128, o0 = blockIdx.x * 128;
    const int b = m0 >> 10, n0 = m0 & 1023;

    float acc[2][8][4];
#pragma unroll
    for (int i = 0; i < 2; i++)
#pragma unroll
        for (int j = 0; j < 8; j++)
#pragma unroll
            for (int q = 0; q < 4; q++) acc[i][j][q] = 0.f;

    for (int ck = 0; ck < 16; ck++) {
        __syncthreads();
#pragma unroll
        for (int it = 0; it < 8; it++) {              // A from g_ao (k fastest)
            int idx = tid + it * 256; int k2 = idx & 15, m = idx >> 4;
            float2 av = *(const float2*)&g_ao[(m0 + m) * 512 + ck * 32 + 2 * k2];
            bf h0, l0, h1, l1; bsplit(av.x, h0, l0); bsplit(av.y, h1, l1);
            bf2 ph; ph.x = h0; ph.y = h1;
            bf2 pl; pl.x = l0; pl.y = l1;
            *(bf2*)(AH + m * 40 + 2 * k2) = ph;
            *(bf2*)(AL + m * 40 + 2 * k2) = pl;
        }
#pragma unroll
        for (int it = 0; it < 8; it++) {              // B 128o x 32k
            int idx = tid + it * 256; int oo = idx & 127, k2 = idx >> 7;
            float v0 = w[(ck * 32 + 2 * k2) * 512 + o0 + oo];
            float v1 = w[(ck * 32 + 2 * k2 + 1) * 512 + o0 + oo];
            bf h0, l0, h1, l1; bsplit(v0, h0, l0); bsplit(v1, h1, l1);
            bf2 ph; ph.x = h0; ph.y = h1;
            bf2 pl; pl.x = l0; pl.y = l1;
            *(bf2*)(BH + oo * 40 + 2 * k2) = ph;
            *(bf2*)(BL + oo * 40 + 2 * k2) = pl;
        }
        __syncthreads();
#pragma unroll
        for (int ks = 0; ks < 2; ks++) {
            const int kb = ks * 16;
            uint32_t ah[2][4], al[2][4];
#pragma unroll
            for (int mt = 0; mt < 2; mt++) {
                int rb = wm * 32 + mt * 16;
                ah[mt][0] = ldu32(AH + (rb + g) * 40 + kb + 2 * tg);
                ah[mt][1] = ldu32(AH + (rb + g + 8) * 40 + kb + 2 * tg);
                ah[mt][2] = ldu32(AH + (rb + g) * 40 + kb + 2 * tg + 8);
                ah[mt][3] = ldu32(AH + (rb + g + 8) * 40 + kb + 2 * tg + 8);
                al[mt][0] = ldu32(AL + (rb + g) * 40 + kb + 2 * tg);
                al[mt][1] = ldu32(AL + (rb + g + 8) * 40 + kb + 2 * tg);
                al[mt][2] = ldu32(AL + (rb + g) * 40 + kb + 2 * tg + 8);
                al[mt][3] = ldu32(AL + (rb + g + 8) * 40 + kb + 2 * tg + 8);
            }
#pragma unroll
            for (int nt = 0; nt < 8; nt++) {
                int nb = wn * 64 + nt * 8 + g;
                uint32_t bh0 = ldu32(BH + nb * 40 + kb + 2 * tg);
                uint32_t bh1 = ldu32(BH + nb * 40 + kb + 2 * tg + 8);
                uint32_t bl0 = ldu32(BL + nb * 40 + kb + 2 * tg);
                uint32_t bl1 = ldu32(BL + nb * 40 + kb + 2 * tg + 8);
#pragma unroll
                for (int mt = 0; mt < 2; mt++) {
                    mma_bf(acc[mt][nt], ah[mt], bh0, bh1);
                    mma_bf(acc[mt][nt], ah[mt], bl0, bl1);
                    mma_bf(acc[mt][nt], al[mt], bh0, bh1);
                }
            }
        }
    }
    __syncthreads();
    float* stg = (float*)sm;                          // [128][130]
#pragma unroll
    for (int mt = 0; mt < 2; mt++)
#pragma unroll
        for (int nt = 0; nt < 8; nt++) {
            int r0 = wm * 32 + mt * 16 + g, c = wn * 64 + nt * 8 + 2 * tg;
            stg[r0 * 130 + c]       = acc[mt][nt][0];
            stg[r0 * 130 + c + 1]   = acc[mt][nt][1];
            stg[(r0 + 8) * 130 + c]     = acc[mt][nt][2];
            stg[(r0 + 8) * 130 + c + 1] = acc[mt][nt][3];
        }
    __syncthreads();
    for (int j = 0; j < 64; j++) {                    // lanes vary n
        int idx = tid + j * 256; int rr = idx & 127, oc = idx >> 7;
        int oo = o0 + oc;
        int gi = ((b * 512 + oo) << 10) + n0 + rr;
        out[gi] = stg[rr * 130 + oc] + bias[oo] + x[gi];
    }
}

// ---------------------------------------------------------------------------
extern "C" void kernel_launch(void* const* d_in, const int* in_sizes, int n_in,
                              void* d_out, int out_size)
{
    const float* x      = (const float*)d_in[0];
    const float* w_proj = (const float*)d_in[1];
    const float* b_proj = (const float*)d_in[2];
    const float* w_out  = (const float*)d_in[3];
    const float* b_out  = (const float*)d_in[4];
    float* out = (float*)d_out;

    cudaFuncSetAttribute(gemm_qkv,    cudaFuncAttributeMaxDynamicSharedMemorySize, GEMM_SMEM);
    cudaFuncSetAttribute(attn_kernel, cudaFuncAttributeMaxDynamicSharedMemorySize, ATTN_SMEM);
    cudaFuncSetAttribute(gemm_out,    cudaFuncAttributeMaxDynamicSharedMemorySize, GEMM_SMEM);

    gemm_qkv<<<dim3(12, 128), 256, GEMM_SMEM>>>(x, w_proj, b_proj);
    attn_kernel<<<dim3(8, 128), 256, ATTN_SMEM>>>();
    gemm_out<<<dim3(4, 128), 256, GEMM_SMEM>>>(w_out, b_out, x, out);
}

// round 9
// speedup vs baseline: 2.3188x; 1.0169x over previous
#include <cuda_runtime.h>
#include <cuda_bf16.h>
#include <cstdint>

#define NTOK 1024
#define QKVOUT 1536

typedef __nv_bfloat16 bf;
typedef __nv_bfloat162 bf2;

// Same static footprint as the passing R5 (4 x 32 MiB). Contents are now
// packed bf16 hi/lo pairs (hi = low 16 bits) instead of f32.
__device__ float g_q [16*8*NTOK*64];   // [bh][n][d]  (Q pre-scaled by 0.125)
__device__ float g_k [16*8*NTOK*64];   // [bh][n][d]
__device__ float g_vT[16*8*64*NTOK];   // [bh][d][n]
__device__ float g_ao[16*NTOK*512];    // [m][h*64+d]

__device__ __forceinline__ void bsplit(float v, bf& h, bf& l) {
    h = __float2bfloat16(v);
    l = __float2bfloat16(v - __bfloat162float(h));
}
__device__ __forceinline__ uint32_t bpack(float v) {
    bf h, l; bsplit(v, h, l);
    return (uint32_t)__bfloat16_as_ushort(h) |
           ((uint32_t)__bfloat16_as_ushort(l) << 16);
}
__device__ __forceinline__ void mma_bf(float* c, const uint32_t* a,
                                       uint32_t b0, uint32_t b1) {
    asm volatile(
        "mma.sync.aligned.m16n8k16.row.col.f32.bf16.bf16.f32 "
        "{%0,%1,%2,%3}, {%4,%5,%6,%7}, {%8,%9}, {%0,%1,%2,%3};"
        : "+f"(c[0]), "+f"(c[1]), "+f"(c[2]), "+f"(c[3])
        : "r"(a[0]), "r"(a[1]), "r"(a[2]), "r"(a[3]), "r"(b0), "r"(b1));
}
__device__ __forceinline__ uint32_t ldu32(const bf* p) {
    return *(const uint32_t*)p;
}

// ============ Kernel 1: QKV projection (bf16x3 mma.sync) ====================
// smem: AH 0 | AL | BH | BL (each 128*40 bf) ; epilogue stage f32[128][130]
#define GEMM_SMEM 66560

__global__ __launch_bounds__(256)
void gemm_qkv(const float* __restrict__ x, const float* __restrict__ w,
              const float* __restrict__ bias)
{
    extern __shared__ char sm[];
    bf* AH = (bf*)sm;            bf* AL = AH + 128*40;
    bf* BH = AL + 128*40;        bf* BL = BH + 128*40;

    const int tid = threadIdx.x, wid = tid >> 5, lane = tid & 31;
    const int g = lane >> 2, tg = lane & 3;
    const int wm = wid & 3, wn = wid >> 2;
    const int m0 = blockIdx.y * 128, o0 = blockIdx.x * 128;
    const int b = m0 >> 10, n0 = m0 & 1023;
    const float* Ab = x + b * 512 * NTOK + n0;

    float acc[2][8][4];
#pragma unroll
    for (int i = 0; i < 2; i++)
#pragma unroll
        for (int j = 0; j < 8; j++)
#pragma unroll
            for (int q = 0; q < 4; q++) acc[i][j][q] = 0.f;

    for (int ck = 0; ck < 16; ck++) {
        __syncthreads();
#pragma unroll
        for (int it = 0; it < 8; it++) {              // A 128m x 32k
            int idx = tid + it * 256; int m = idx & 127, k2 = idx >> 7;
            float v0 = Ab[(ck * 32 + 2 * k2) * NTOK + m];
            float v1 = Ab[(ck * 32 + 2 * k2 + 1) * NTOK + m];
            bf h0, l0, h1, l1; bsplit(v0, h0, l0); bsplit(v1, h1, l1);
            bf2 ph; ph.x = h0; ph.y = h1;
            bf2 pl; pl.x = l0; pl.y = l1;
            *(bf2*)(AH + m * 40 + 2 * k2) = ph;
            *(bf2*)(AL + m * 40 + 2 * k2) = pl;
        }
#pragma unroll
        for (int it = 0; it < 8; it++) {              // B 128o x 32k
            int idx = tid + it * 256; int oo = idx & 127, k2 = idx >> 7;
            float v0 = w[(ck * 32 + 2 * k2) * QKVOUT + o0 + oo];
            float v1 = w[(ck * 32 + 2 * k2 + 1) * QKVOUT + o0 + oo];
            bf h0, l0, h1, l1; bsplit(v0, h0, l0); bsplit(v1, h1, l1);
            bf2 ph; ph.x = h0; ph.y = h1;
            bf2 pl; pl.x = l0; pl.y = l1;
            *(bf2*)(BH + oo * 40 + 2 * k2) = ph;
            *(bf2*)(BL + oo * 40 + 2 * k2) = pl;
        }
        __syncthreads();
#pragma unroll
        for (int ks = 0; ks < 2; ks++) {
            const int kb = ks * 16;
            uint32_t ah[2][4], al[2][4];
#pragma unroll
            for (int mt = 0; mt < 2; mt++) {
                int rb = wm * 32 + mt * 16;
                ah[mt][0] = ldu32(AH + (rb + g) * 40 + kb + 2 * tg);
                ah[mt][1] = ldu32(AH + (rb + g + 8) * 40 + kb + 2 * tg);
                ah[mt][2] = ldu32(AH + (rb + g) * 40 + kb + 2 * tg + 8);
                ah[mt][3] = ldu32(AH + (rb + g + 8) * 40 + kb + 2 * tg + 8);
                al[mt][0] = ldu32(AL + (rb + g) * 40 + kb + 2 * tg);
                al[mt][1] = ldu32(AL + (rb + g + 8) * 40 + kb + 2 * tg);
                al[mt][2] = ldu32(AL + (rb + g) * 40 + kb + 2 * tg + 8);
                al[mt][3] = ldu32(AL + (rb + g + 8) * 40 + kb + 2 * tg + 8);
            }
#pragma unroll
            for (int nt = 0; nt < 8; nt++) {
                int nb = wn * 64 + nt * 8 + g;
                uint32_t bh0 = ldu32(BH + nb * 40 + kb + 2 * tg);
                uint32_t bh1 = ldu32(BH + nb * 40 + kb + 2 * tg + 8);
                uint32_t bl0 = ldu32(BL + nb * 40 + kb + 2 * tg);
                uint32_t bl1 = ldu32(BL + nb * 40 + kb + 2 * tg + 8);
#pragma unroll
                for (int mt = 0; mt < 2; mt++) {
                    mma_bf(acc[mt][nt], ah[mt], bh0, bh1);
                    mma_bf(acc[mt][nt], ah[mt], bl0, bl1);
                    mma_bf(acc[mt][nt], al[mt], bh0, bh1);
                }
            }
        }
    }
    __syncthreads();
    float* stg = (float*)sm;                          // [128][130]
#pragma unroll
    for (int mt = 0; mt < 2; mt++)
#pragma unroll
        for (int nt = 0; nt < 8; nt++) {
            int r0 = wm * 32 + mt * 16 + g, c = wn * 64 + nt * 8 + 2 * tg;
            stg[r0 * 130 + c]           = acc[mt][nt][0];
            stg[r0 * 130 + c + 1]       = acc[mt][nt][1];
            stg[(r0 + 8) * 130 + c]     = acc[mt][nt][2];
            stg[(r0 + 8) * 130 + c + 1] = acc[mt][nt][3];
        }
    __syncthreads();
    for (int j = 0; j < 64; j++) {                    // q,k: lanes vary o
        int idx = tid + j * 256; int oc = idx & 127, rr = idx >> 7;
        int o = o0 + oc, head = o / 192, r2 = o - head * 192;
        if (r2 < 128) {
            float val = stg[rr * 130 + oc] + bias[o];
            if (r2 < 64) val *= 0.125f;               // fold attn scale into Q
            uint32_t* dst = (uint32_t*)((r2 < 64) ? g_q : g_k);
            dst[(((b * 8 + head) << 10) + n0 + rr) * 64 + (r2 & 63)] = bpack(val);
        }
    }
    for (int j = 0; j < 64; j++) {                    // vT: lanes vary n
        int idx = tid + j * 256; int rr = idx & 127, oc = idx >> 7;
        int o = o0 + oc, head = o / 192, r2 = o - head * 192;
        if (r2 >= 128)
            ((uint32_t*)g_vT)[((b * 8 + head) * 64 + (r2 - 128)) * 1024 + n0 + rr] =
                bpack(stg[rr * 130 + oc] + bias[o]);
    }
}

// ============ Kernel 2: attention (bf16x3 mma.sync flash) ===================
// bytes: QH 0 QL 18432 KH 36864 KL 46080 VH 55296 VL 64512 SS 73728(f32 128x68)
//        PH 108544 PL 126976 ; total 145408
#define ATTN_SMEM 145408

__global__ __launch_bounds__(256)
void attn_kernel()
{
    extern __shared__ char sm[];
    bf* QH = (bf*)sm;              bf* QL = QH + 128*72;
    bf* KH = QL + 128*72;          bf* KL = KH + 64*72;
    bf* VH = KL + 64*72;           bf* VL = VH + 64*72;
    float* SS = (float*)(sm + 73728);                 // [128][68]
    bf* PH = (bf*)(sm + 108544);   bf* PL = PH + 128*72;
    __shared__ float m_row[128], l_row[128], corr_row[128];

    const int tid = threadIdx.x, wid = tid >> 5, lane = tid & 31;
    const int g = lane >> 2, tg = lane & 3;
    const int wm = wid & 3, wn = wid >> 2;
    const int bh = blockIdx.y, q0 = blockIdx.x * 128;
    const uint32_t* Qg = (const uint32_t*)g_q  + (size_t)bh * (NTOK * 64);
    const uint32_t* Kg = (const uint32_t*)g_k  + (size_t)bh * (NTOK * 64);
    const uint32_t* Vg = (const uint32_t*)g_vT + (size_t)bh * (64 * NTOK);

    if (tid < 128) { m_row[tid] = -1e30f; l_row[tid] = 0.f; }

#pragma unroll 4
    for (int it = 0; it < 16; it++) {                 // Q 128x64 (packed)
        int idx = tid + it * 256; int d2 = idx & 31, q = idx >> 5;
        uint2 wv = *(const uint2*)(Qg + (q0 + q) * 64 + 2 * d2);
        *(uint32_t*)(QH + q * 72 + 2 * d2) = __byte_perm(wv.x, wv.y, 0x5410);
        *(uint32_t*)(QL + q * 72 + 2 * d2) = __byte_perm(wv.x, wv.y, 0x7632);
    }
    float o[2][4][4];
#pragma unroll
    for (int i = 0; i < 2; i++)
#pragma unroll
        for (int j = 0; j < 4; j++)
#pragma unroll
            for (int q = 0; q < 4; q++) o[i][j][q] = 0.f;

    for (int t = 0; t < 16; t++) {
        __syncthreads();
#pragma unroll
        for (int it = 0; it < 8; it++) {              // K 64x64 (packed)
            int idx = tid + it * 256; int d2 = idx & 31, r = idx >> 5;
            uint2 wv = *(const uint2*)(Kg + (t * 64 + r) * 64 + 2 * d2);
            *(uint32_t*)(KH + r * 72 + 2 * d2) = __byte_perm(wv.x, wv.y, 0x5410);
            *(uint32_t*)(KL + r * 72 + 2 * d2) = __byte_perm(wv.x, wv.y, 0x7632);
        }
#pragma unroll
        for (int it = 0; it < 8; it++) {              // V [d][key] 64x64 (packed)
            int idx = tid + it * 256; int k2 = idx & 31, d = idx >> 5;
            uint2 wv = *(const uint2*)(Vg + d * 1024 + t * 64 + 2 * k2);
            *(uint32_t*)(VH + d * 72 + 2 * k2) = __byte_perm(wv.x, wv.y, 0x5410);
            *(uint32_t*)(VL + d * 72 + 2 * k2) = __byte_perm(wv.x, wv.y, 0x7632);
        }
        __syncthreads();
        float s[2][4][4];                             // S = Q K^T (Q pre-scaled)
#pragma unroll
        for (int i = 0; i < 2; i++)
#pragma unroll
            for (int j = 0; j < 4; j++)
#pragma unroll
                for (int q = 0; q < 4; q++) s[i][j][q] = 0.f;
#pragma unroll
        for (int ks = 0; ks < 4; ks++) {
            const int kb = ks * 16;
            uint32_t ah[2][4], al[2][4];
#pragma unroll
            for (int mt = 0; mt < 2; mt++) {
                int rb = wm * 32 + mt * 16;
                ah[mt][0] = ldu32(QH + (rb + g) * 72 + kb + 2 * tg);
                ah[mt][1] = ldu32(QH + (rb + g + 8) * 72 + kb + 2 * tg);
                ah[mt][2] = ldu32(QH + (rb + g) * 72 + kb + 2 * tg + 8);
                ah[mt][3] = ldu32(QH + (rb + g + 8) * 72 + kb + 2 * tg + 8);
                al[mt][0] = ldu32(QL + (rb + g) * 72 + kb + 2 * tg);
                al[mt][1] = ldu32(QL + (rb + g + 8) * 72 + kb + 2 * tg);
                al[mt][2] = ldu32(QL + (rb + g) * 72 + kb + 2 * tg + 8);
                al[mt][3] = ldu32(QL + (rb + g + 8) * 72 + kb + 2 * tg + 8);
            }
#pragma unroll
            for (int nt = 0; nt < 4; nt++) {
                int nb = wn * 32 + nt * 8 + g;
                uint32_t bh0 = ldu32(KH + nb * 72 + kb + 2 * tg);
                uint32_t bh1 = ldu32(KH + nb * 72 + kb + 2 * tg + 8);
                uint32_t bl0 = ldu32(KL + nb * 72 + kb + 2 * tg);
                uint32_t bl1 = ldu32(KL + nb * 72 + kb + 2 * tg + 8);
#pragma unroll
                for (int mt = 0; mt < 2; mt++) {
                    mma_bf(s[mt][nt], ah[mt], bh0, bh1);
                    mma_bf(s[mt][nt], ah[mt], bl0, bl1);
                    mma_bf(s[mt][nt], al[mt], bh0, bh1);
                }
            }
        }
#pragma unroll
        for (int mt = 0; mt < 2; mt++)
#pragma unroll
            for (int nt = 0; nt < 4; nt++) {
                int r0 = wm * 32 + mt * 16 + g, c = wn * 32 + nt * 8 + 2 * tg;
                float2 v0; v0.x = s[mt][nt][0]; v0.y = s[mt][nt][1];
                float2 v1; v1.x = s[mt][nt][2]; v1.y = s[mt][nt][3];
                *(float2*)&SS[r0 * 68 + c] = v0;
                *(float2*)&SS[(r0 + 8) * 68 + c] = v1;
            }
        __syncthreads();
        {                                             // softmax: 2 thr/row
            int row = tid >> 1, half = tid & 1, cb = half * 32;
            float mo = m_row[row];
            float lm = -1e30f;
#pragma unroll 8
            for (int i = 0; i < 32; i++) lm = fmaxf(lm, SS[row * 68 + cb + i]);
            lm = fmaxf(lm, __shfl_xor_sync(0xffffffffu, lm, 1));
            float mn = fmaxf(mo, lm);
            float corr = __expf(mo - mn);
            float ps = 0.f;
#pragma unroll 8
            for (int i = 0; i < 32; i++) {
                float p = __expf(SS[row * 68 + cb + i] - mn);
                bf ph = __float2bfloat16(p);
                bf pl = __float2bfloat16(p - __bfloat162float(ph));
                PH[row * 72 + cb + i] = ph;
                PL[row * 72 + cb + i] = pl;
                ps += __bfloat162float(ph) + __bfloat162float(pl);
            }
            ps += __shfl_xor_sync(0xffffffffu, ps, 1);
            if (half == 0) {
                m_row[row] = mn;
                l_row[row] = l_row[row] * corr + ps;
                corr_row[row] = corr;
            }
        }
        __syncthreads();
#pragma unroll
        for (int mt = 0; mt < 2; mt++) {              // rescale O
            float c0 = corr_row[wm * 32 + mt * 16 + g];
            float c1 = corr_row[wm * 32 + mt * 16 + g + 8];
#pragma unroll
            for (int nt = 0; nt < 4; nt++) {
                o[mt][nt][0] *= c0; o[mt][nt][1] *= c0;
                o[mt][nt][2] *= c1; o[mt][nt][3] *= c1;
            }
        }
#pragma unroll
        for (int ks = 0; ks < 4; ks++) {              // O += P V
            const int kb = ks * 16;
            uint32_t ah[2][4], al[2][4];
#pragma unroll
            for (int mt = 0; mt < 2; mt++) {
                int rb = wm * 32 + mt * 16;
                ah[mt][0] = ldu32(PH + (rb + g) * 72 + kb + 2 * tg);
                ah[mt][1] = ldu32(PH + (rb + g + 8) * 72 + kb + 2 * tg);
                ah[mt][2] = ldu32(PH + (rb + g) * 72 + kb + 2 * tg + 8);
                ah[mt][3] = ldu32(PH + (rb + g + 8) * 72 + kb + 2 * tg + 8);
                al[mt][0] = ldu32(PL + (rb + g) * 72 + kb + 2 * tg);
                al[mt][1] = ldu32(PL + (rb + g + 8) * 72 + kb + 2 * tg);
                al[mt][2] = ldu32(PL + (rb + g) * 72 + kb + 2 * tg + 8);
                al[mt][3] = ldu32(PL + (rb + g + 8) * 72 + kb + 2 * tg + 8);
            }
#pragma unroll
            for (int nt = 0; nt < 4; nt++) {
                int nb = wn * 32 + nt * 8 + g;
                uint32_t bh0 = ldu32(VH + nb * 72 + kb + 2 * tg);
                uint32_t bh1 = ldu32(VH + nb * 72 + kb + 2 * tg + 8);
                uint32_t bl0 = ldu32(VL + nb * 72 + kb + 2 * tg);
                uint32_t bl1 = ldu32(VL + nb * 72 + kb + 2 * tg + 8);
#pragma unroll
                for (int mt = 0; mt < 2; mt++) {
                    mma_bf(o[mt][nt], ah[mt], bh0, bh1);
                    mma_bf(o[mt][nt], ah[mt], bl0, bl1);
                    mma_bf(o[mt][nt], al[mt], bh0, bh1);
                }
            }
        }
    }
    __syncthreads();
    float* ostg = SS;                                 // [128][65]
#pragma unroll
    for (int mt = 0; mt < 2; mt++) {
        int r0 = wm * 32 + mt * 16 + g;
        float i0 = 1.f / l_row[r0], i1 = 1.f / l_row[r0 + 8];
#pragma unroll
        for (int nt = 0; nt < 4; nt++) {
            int c = wn * 32 + nt * 8 + 2 * tg;
            ostg[r0 * 65 + c]           = o[mt][nt][0] * i0;
            ostg[r0 * 65 + c + 1]       = o[mt][nt][1] * i0;
            ostg[(r0 + 8) * 65 + c]     = o[mt][nt][2] * i1;
            ostg[(r0 + 8) * 65 + c + 1] = o[mt][nt][3] * i1;
        }
    }
    __syncthreads();
    const int bb = bh >> 3, hh = bh & 7;
    for (int j = 0; j < 32; j++) {
        int idx = tid + j * 256; int d = idx & 63, rr = idx >> 6;
        ((uint32_t*)g_ao)[((bb << 10) + q0 + rr) * 512 + hh * 64 + d] =
            bpack(ostg[rr * 65 + d]);
    }
}

// ============ Kernel 3: out projection + bias + residual ====================
__global__ __launch_bounds__(256)
void gemm_out(const float* __restrict__ w, const float* __restrict__ bias,
              const float* __restrict__ x, float* __restrict__ out)
{
    extern __shared__ char sm[];
    bf* AH = (bf*)sm;            bf* AL = AH + 128*40;
    bf* BH = AL + 128*40;        bf* BL = BH + 128*40;

    const int tid = threadIdx.x, wid = tid >> 5, lane = tid & 31;
    const int g = lane >> 2, tg = lane & 3;
    const int wm = wid & 3, wn = wid >> 2;
    const int m0 = blockIdx.y * 128, o0 = blockIdx.x * 128;
    const int b = m0 >> 10, n0 = m0 & 1023;

    float acc[2][8][4];
#pragma unroll
    for (int i = 0; i < 2; i++)
#pragma unroll
        for (int j = 0; j < 8; j++)
#pragma unroll
            for (int q = 0; q < 4; q++) acc[i][j][q] = 0.f;

    for (int ck = 0; ck < 16; ck++) {
        __syncthreads();
#pragma unroll
        for (int it = 0; it < 8; it++) {              // A from packed g_ao
            int idx = tid + it * 256; int k2 = idx & 15, m = idx >> 4;
            uint2 wv = *(const uint2*)((const uint32_t*)g_ao +
                        (size_t)(m0 + m) * 512 + ck * 32 + 2 * k2);
            *(uint32_t*)(AH + m * 40 + 2 * k2) = __byte_perm(wv.x, wv.y, 0x5410);
            *(uint32_t*)(AL + m * 40 + 2 * k2) = __byte_perm(wv.x, wv.y, 0x7632);
        }
#pragma unroll
        for (int it = 0; it < 8; it++) {              // B 128o x 32k (f32 split)
            int idx = tid + it * 256; int oo = idx & 127, k2 = idx >> 7;
            float v0 = w[(ck * 32 + 2 * k2) * 512 + o0 + oo];
            float v1 = w[(ck * 32 + 2 * k2 + 1) * 512 + o0 + oo];
            bf h0, l0, h1, l1; bsplit(v0, h0, l0); bsplit(v1, h1, l1);
            bf2 ph; ph.x = h0; ph.y = h1;
            bf2 pl; pl.x = l0; pl.y = l1;
            *(bf2*)(BH + oo * 40 + 2 * k2) = ph;
            *(bf2*)(BL + oo * 40 + 2 * k2) = pl;
        }
        __syncthreads();
#pragma unroll
        for (int ks = 0; ks < 2; ks++) {
            const int kb = ks * 16;
            uint32_t ah[2][4], al[2][4];
#pragma unroll
            for (int mt = 0; mt < 2; mt++) {
                int rb = wm * 32 + mt * 16;
                ah[mt][0] = ldu32(AH + (rb + g) * 40 + kb + 2 * tg);
                ah[mt][1] = ldu32(AH + (rb + g + 8) * 40 + kb + 2 * tg);
                ah[mt][2] = ldu32(AH + (rb + g) * 40 + kb + 2 * tg + 8);
                ah[mt][3] = ldu32(AH + (rb + g + 8) * 40 + kb + 2 * tg + 8);
                al[mt][0] = ldu32(AL + (rb + g) * 40 + kb + 2 * tg);
                al[mt][1] = ldu32(AL + (rb + g + 8) * 40 + kb + 2 * tg);
                al[mt][2] = ldu32(AL + (rb + g) * 40 + kb + 2 * tg + 8);
                al[mt][3] = ldu32(AL + (rb + g + 8) * 40 + kb + 2 * tg + 8);
            }
#pragma unroll
            for (int nt = 0; nt < 8; nt++) {
                int nb = wn * 64 + nt * 8 + g;
                uint32_t bh0 = ldu32(BH + nb * 40 + kb + 2 * tg);
                uint32_t bh1 = ldu32(BH + nb * 40 + kb + 2 * tg + 8);
                uint32_t bl0 = ldu32(BL + nb * 40 + kb + 2 * tg);
                uint32_t bl1 = ldu32(BL + nb * 40 + kb + 2 * tg + 8);
#pragma unroll
                for (int mt = 0; mt < 2; mt++) {
                    mma_bf(acc[mt][nt], ah[mt], bh0, bh1);
                    mma_bf(acc[mt][nt], ah[mt], bl0, bl1);
                    mma_bf(acc[mt][nt], al[mt], bh0, bh1);
                }
            }
        }
    }
    __syncthreads();
    float* stg = (float*)sm;                          // [128][130]
#pragma unroll
    for (int mt = 0; mt < 2; mt++)
#pragma unroll
        for (int nt = 0; nt < 8; nt++) {
            int r0 = wm * 32 + mt * 16 + g, c = wn * 64 + nt * 8 + 2 * tg;
            stg[r0 * 130 + c]           = acc[mt][nt][0];
            stg[r0 * 130 + c + 1]       = acc[mt][nt][1];
            stg[(r0 + 8) * 130 + c]     = acc[mt][nt][2];
            stg[(r0 + 8) * 130 + c + 1] = acc[mt][nt][3];
        }
    __syncthreads();
    for (int j = 0; j < 64; j++) {                    // lanes vary n
        int idx = tid + j * 256; int rr = idx & 127, oc = idx >> 7;
        int oo = o0 + oc;
        int gi = ((b * 512 + oo) << 10) + n0 + rr;
        out[gi] = stg[rr * 130 + oc] + bias[oo] + x[gi];
    }
}

// ---------------------------------------------------------------------------
extern "C" void kernel_launch(void* const* d_in, const int* in_sizes, int n_in,
                              void* d_out, int out_size)
{
    const float* x      = (const float*)d_in[0];
    const float* w_proj = (const float*)d_in[1];
    const float* b_proj = (const float*)d_in[2];
    const float* w_out  = (const float*)d_in[3];
    const float* b_out  = (const float*)d_in[4];
    float* out = (float*)d_out;

    cudaFuncSetAttribute(gemm_qkv,    cudaFuncAttributeMaxDynamicSharedMemorySize, GEMM_SMEM);
    cudaFuncSetAttribute(attn_kernel, cudaFuncAttributeMaxDynamicSharedMemorySize, ATTN_SMEM);
    cudaFuncSetAttribute(gemm_out,    cudaFuncAttributeMaxDynamicSharedMemorySize, GEMM_SMEM);

    gemm_qkv<<<dim3(12, 128), 256, GEMM_SMEM>>>(x, w_proj, b_proj);
    attn_kernel<<<dim3(8, 128), 256, ATTN_SMEM>>>();
    gemm_out<<<dim3(4, 128), 256, GEMM_SMEM>>>(w_out, b_out, x, out);
}